// round 4
// baseline (speedup 1.0000x reference)
#include <cuda_runtime.h>
#include <math.h>

// ---------------------------------------------------------------------------
// Scratch: node state and aggregation buffer. N = 1,000,000 fits in 1<<20.
// ---------------------------------------------------------------------------
#define MAXN (1 << 20)
__device__ float2 g_xn[MAXN];
__device__ float2 g_agg[MAXN];
__device__ int    g_idx64;   // 1 if edge_index is int64, 0 if int32

#define EPSF 1e-15f

__device__ __forceinline__ void red_add_f32x2(float2* p, float vx, float vy) {
    asm volatile("red.global.add.v2.f32 [%0], {%1, %2};"
                 :: "l"(p), "f"(vx), "f"(vy)
                 : "memory");
}

// ---------------------------------------------------------------------------
// Kernel 0: index dtype detection (int32 vs int64), single block.
// ---------------------------------------------------------------------------
__global__ void k_detect(const long long* __restrict__ ei, long long n_words, int N) {
    __shared__ int bad;
    if (threadIdx.x == 0) bad = 0;
    __syncthreads();
    long long lim = n_words < 2048 ? n_words : 2048;
    int local_bad = 0;
    for (long long i = threadIdx.x; i < lim; i += blockDim.x) {
        long long v = ei[i];
        if (v < 0 || v >= (long long)N) local_bad = 1;
    }
    if (local_bad) bad = 1;
    __syncthreads();
    if (threadIdx.x == 0) g_idx64 = bad ? 0 : 1;
}

// ---------------------------------------------------------------------------
// Kernel 1: normalize input x into g_xn, zero g_agg.
// ---------------------------------------------------------------------------
__global__ void k_init(const float2* __restrict__ x, int N) {
    int i = blockIdx.x * blockDim.x + threadIdx.x;
    if (i >= N) return;
    float2 v = x[i];
    float inv = 1.0f / (sqrtf(v.x * v.x + v.y * v.y) + EPSF);
    g_xn[i] = make_float2(v.x * inv, v.y * inv);
    g_agg[i] = make_float2(0.0f, 0.0f);
}

// ---------------------------------------------------------------------------
// Kernel 2: edge scatter, 8 edges per loop iteration.
// Batch all 8 independent gathers before the 8 reds so the gather latencies
// overlap each other and the red issue overlaps the next batch's loads.
// Index loads use __ldcs (streamed once, no cache pollution).
// ---------------------------------------------------------------------------
__global__ void __launch_bounds__(256) k_scatter(const void* __restrict__ eiv, long long E) {
    long long tid    = (long long)blockIdx.x * blockDim.x + threadIdx.x;
    long long stride = (long long)gridDim.x * blockDim.x;

    if (g_idx64 == 0) {
        const int* src = (const int*)eiv;
        const int* dst = src + E;
        long long octs = E >> 3;              // 8 edges per iteration
        for (long long q = tid; q < octs; q += stride) {
            int4 s0 = __ldcs((const int4*)(src + 8 * q));
            int4 s1 = __ldcs((const int4*)(src + 8 * q) + 1);
            int4 d0 = __ldcs((const int4*)(dst + 8 * q));
            int4 d1 = __ldcs((const int4*)(dst + 8 * q) + 1);
            float2 v0 = g_xn[s0.x];
            float2 v1 = g_xn[s0.y];
            float2 v2 = g_xn[s0.z];
            float2 v3 = g_xn[s0.w];
            float2 v4 = g_xn[s1.x];
            float2 v5 = g_xn[s1.y];
            float2 v6 = g_xn[s1.z];
            float2 v7 = g_xn[s1.w];
            red_add_f32x2(&g_agg[d0.x], v0.x, v0.y);
            red_add_f32x2(&g_agg[d0.y], v1.x, v1.y);
            red_add_f32x2(&g_agg[d0.z], v2.x, v2.y);
            red_add_f32x2(&g_agg[d0.w], v3.x, v3.y);
            red_add_f32x2(&g_agg[d1.x], v4.x, v4.y);
            red_add_f32x2(&g_agg[d1.y], v5.x, v5.y);
            red_add_f32x2(&g_agg[d1.z], v6.x, v6.y);
            red_add_f32x2(&g_agg[d1.w], v7.x, v7.y);
        }
        if (tid == 0) {
            for (long long e = octs * 8; e < E; e++) {
                float2 v = g_xn[src[e]];
                red_add_f32x2(&g_agg[dst[e]], v.x, v.y);
            }
        }
    } else {
        const long long* src = (const long long*)eiv;
        const long long* dst = src + E;
        long long quads = E >> 2;
        for (long long p = tid; p < quads; p += stride) {
            longlong2 s0 = __ldcs((const longlong2*)(src + 4 * p));
            longlong2 s1 = __ldcs((const longlong2*)(src + 4 * p) + 1);
            longlong2 d0 = __ldcs((const longlong2*)(dst + 4 * p));
            longlong2 d1 = __ldcs((const longlong2*)(dst + 4 * p) + 1);
            float2 v0 = g_xn[(int)s0.x];
            float2 v1 = g_xn[(int)s0.y];
            float2 v2 = g_xn[(int)s1.x];
            float2 v3 = g_xn[(int)s1.y];
            red_add_f32x2(&g_agg[(int)d0.x], v0.x, v0.y);
            red_add_f32x2(&g_agg[(int)d0.y], v1.x, v1.y);
            red_add_f32x2(&g_agg[(int)d1.x], v2.x, v2.y);
            red_add_f32x2(&g_agg[(int)d1.y], v3.x, v3.y);
        }
        if (tid == 0) {
            for (long long e = quads * 4; e < E; e++) {
                float2 v = g_xn[(int)src[e]];
                red_add_f32x2(&g_agg[(int)dst[e]], v.x, v.y);
            }
        }
    }
}

// ---------------------------------------------------------------------------
// Kernel 3: mid-iteration: y = relu(agg @ W); renormalize; zero g_agg.
// ---------------------------------------------------------------------------
__global__ void k_mid(const float* __restrict__ W, int N) {
    int i = blockIdx.x * blockDim.x + threadIdx.x;
    if (i >= N) return;
    float w00 = W[0], w01 = W[1], w10 = W[2], w11 = W[3];
    float2 a = g_agg[i];
    float y0 = fmaxf(fmaf(a.y, w10, a.x * w00), 0.0f);
    float y1 = fmaxf(fmaf(a.y, w11, a.x * w01), 0.0f);
    float inv = 1.0f / (sqrtf(y0 * y0 + y1 * y1) + EPSF);
    g_xn[i] = make_float2(y0 * inv, y1 * inv);
    g_agg[i] = make_float2(0.0f, 0.0f);
}

// ---------------------------------------------------------------------------
// Kernel 4: final: y = relu(agg @ W); out = sigmoid(y . final_weight).
// ---------------------------------------------------------------------------
__global__ void k_final(const float* __restrict__ W,
                        const float* __restrict__ fw,
                        float* __restrict__ out, int N) {
    int i = blockIdx.x * blockDim.x + threadIdx.x;
    if (i >= N) return;
    float w00 = W[0], w01 = W[1], w10 = W[2], w11 = W[3];
    float f0 = fw[0], f1 = fw[1];
    float2 a = g_agg[i];
    float y0 = fmaxf(fmaf(a.y, w10, a.x * w00), 0.0f);
    float y1 = fmaxf(fmaf(a.y, w11, a.x * w01), 0.0f);
    float s = fmaf(y1, f1, y0 * f0);
    out[i] = 1.0f / (1.0f + expf(-s));
}

// ---------------------------------------------------------------------------
// Launch: detect -> init -> scatter -> mid -> scatter -> final.
// ---------------------------------------------------------------------------
extern "C" void kernel_launch(void* const* d_in, const int* in_sizes, int n_in,
                              void* d_out, int out_size) {
    const float* x  = (const float*)d_in[0];
    const void*  ei = (const void*)d_in[1];
    const float* W  = (const float*)d_in[2];
    const float* fw = (const float*)d_in[3];
    float* out = (float*)d_out;

    int N = in_sizes[0] / 2;
    long long E = (long long)in_sizes[1] / 2;

    const int TB = 256;
    int nb = (N + TB - 1) / TB;
    const int SCATTER_BLOCKS = 4096;   // grid-stride; ~1M threads over 4M octets

    k_detect<<<1, 256>>>((const long long*)ei, E, N);
    k_init<<<nb, TB>>>((const float2*)x, N);
    k_scatter<<<SCATTER_BLOCKS, TB>>>(ei, E);
    k_mid<<<nb, TB>>>(W, N);
    k_scatter<<<SCATTER_BLOCKS, TB>>>(ei, E);
    k_final<<<nb, TB>>>(W, fw, out, N);

    (void)n_in; (void)out_size;
}

// round 5
// speedup vs baseline: 1.0290x; 1.0290x over previous
#include <cuda_runtime.h>
#include <math.h>

// ---------------------------------------------------------------------------
// Scratch: node state and aggregation buffer. N = 1,000,000 fits in 1<<20.
// ---------------------------------------------------------------------------
#define MAXN (1 << 20)
__device__ float2 g_xn[MAXN];
__device__ float2 g_agg[MAXN];
__device__ int    g_idx64;   // 1 if edge_index is int64, 0 if int32

#define EPSF 1e-15f

__device__ __forceinline__ void red_add_f32x2(float2* p, float vx, float vy) {
    asm volatile("red.global.add.v2.f32 [%0], {%1, %2};"
                 :: "l"(p), "f"(vx), "f"(vy)
                 : "memory");
}

// L2-only 8-byte gather (bypass L1: random access, ~3% L1 hit, save the L1 stage)
__device__ __forceinline__ float2 ldcg_f2(const float2* p) {
    float2 r;
    asm volatile("ld.global.cg.v2.f32 {%0, %1}, [%2];"
                 : "=f"(r.x), "=f"(r.y) : "l"(p));
    return r;
}

// ---------------------------------------------------------------------------
// Kernel 0: index dtype detection (int32 vs int64), single block.
// ---------------------------------------------------------------------------
__global__ void k_detect(const long long* __restrict__ ei, long long n_words, int N) {
    __shared__ int bad;
    if (threadIdx.x == 0) bad = 0;
    __syncthreads();
    long long lim = n_words < 2048 ? n_words : 2048;
    int local_bad = 0;
    for (long long i = threadIdx.x; i < lim; i += blockDim.x) {
        long long v = ei[i];
        if (v < 0 || v >= (long long)N) local_bad = 1;
    }
    if (local_bad) bad = 1;
    __syncthreads();
    if (threadIdx.x == 0) g_idx64 = bad ? 0 : 1;
}

// ---------------------------------------------------------------------------
// Kernel 1: normalize input x into g_xn, zero g_agg.
// ---------------------------------------------------------------------------
__global__ void k_init(const float2* __restrict__ x, int N) {
    int i = blockIdx.x * blockDim.x + threadIdx.x;
    if (i >= N) return;
    float2 v = x[i];
    float inv = 1.0f / (sqrtf(v.x * v.x + v.y * v.y) + EPSF);
    g_xn[i] = make_float2(v.x * inv, v.y * inv);
    g_agg[i] = make_float2(0.0f, 0.0f);
}

// ---------------------------------------------------------------------------
// Kernel 2: edge scatter: g_agg[dst[e]] += g_xn[src[e]].
// 4 edges/iter (R3-proven shape). Index loads streamed (__ldcs, evict-first);
// gathers via ld.global.cg (L2-only). 4 independent gathers batched before
// the 4 reds. This kernel runs at the LTS sector wall (~32B per random op).
// ---------------------------------------------------------------------------
__global__ void __launch_bounds__(256) k_scatter(const void* __restrict__ eiv, long long E) {
    long long tid    = (long long)blockIdx.x * blockDim.x + threadIdx.x;
    long long stride = (long long)gridDim.x * blockDim.x;

    if (g_idx64 == 0) {
        const int* src = (const int*)eiv;
        const int* dst = src + E;
        long long quads = E >> 2;
        for (long long q = tid; q < quads; q += stride) {
            int4 s = __ldcs((const int4*)(src + 4 * q));
            int4 d = __ldcs((const int4*)(dst + 4 * q));
            float2 v0 = ldcg_f2(&g_xn[s.x]);
            float2 v1 = ldcg_f2(&g_xn[s.y]);
            float2 v2 = ldcg_f2(&g_xn[s.z]);
            float2 v3 = ldcg_f2(&g_xn[s.w]);
            red_add_f32x2(&g_agg[d.x], v0.x, v0.y);
            red_add_f32x2(&g_agg[d.y], v1.x, v1.y);
            red_add_f32x2(&g_agg[d.z], v2.x, v2.y);
            red_add_f32x2(&g_agg[d.w], v3.x, v3.y);
        }
        if (tid == 0) {
            for (long long e = quads * 4; e < E; e++) {
                float2 v = ldcg_f2(&g_xn[src[e]]);
                red_add_f32x2(&g_agg[dst[e]], v.x, v.y);
            }
        }
    } else {
        const long long* src = (const long long*)eiv;
        const long long* dst = src + E;
        long long pairs = E >> 1;
        for (long long p = tid; p < pairs; p += stride) {
            longlong2 s = __ldcs((const longlong2*)(src + 2 * p));
            longlong2 d = __ldcs((const longlong2*)(dst + 2 * p));
            float2 v0 = ldcg_f2(&g_xn[(int)s.x]);
            float2 v1 = ldcg_f2(&g_xn[(int)s.y]);
            red_add_f32x2(&g_agg[(int)d.x], v0.x, v0.y);
            red_add_f32x2(&g_agg[(int)d.y], v1.x, v1.y);
        }
        if (tid == 0 && (E & 1LL)) {
            long long e = E - 1;
            float2 v = ldcg_f2(&g_xn[(int)src[e]]);
            red_add_f32x2(&g_agg[(int)dst[e]], v.x, v.y);
        }
    }
}

// ---------------------------------------------------------------------------
// Kernel 3: mid-iteration: y = relu(agg @ W); renormalize; zero g_agg.
// ---------------------------------------------------------------------------
__global__ void k_mid(const float* __restrict__ W, int N) {
    int i = blockIdx.x * blockDim.x + threadIdx.x;
    if (i >= N) return;
    float w00 = W[0], w01 = W[1], w10 = W[2], w11 = W[3];
    float2 a = g_agg[i];
    float y0 = fmaxf(fmaf(a.y, w10, a.x * w00), 0.0f);
    float y1 = fmaxf(fmaf(a.y, w11, a.x * w01), 0.0f);
    float inv = 1.0f / (sqrtf(y0 * y0 + y1 * y1) + EPSF);
    g_xn[i] = make_float2(y0 * inv, y1 * inv);
    g_agg[i] = make_float2(0.0f, 0.0f);
}

// ---------------------------------------------------------------------------
// Kernel 4: final: y = relu(agg @ W); out = sigmoid(y . final_weight).
// ---------------------------------------------------------------------------
__global__ void k_final(const float* __restrict__ W,
                        const float* __restrict__ fw,
                        float* __restrict__ out, int N) {
    int i = blockIdx.x * blockDim.x + threadIdx.x;
    if (i >= N) return;
    float w00 = W[0], w01 = W[1], w10 = W[2], w11 = W[3];
    float f0 = fw[0], f1 = fw[1];
    float2 a = g_agg[i];
    float y0 = fmaxf(fmaf(a.y, w10, a.x * w00), 0.0f);
    float y1 = fmaxf(fmaf(a.y, w11, a.x * w01), 0.0f);
    float s = fmaf(y1, f1, y0 * f0);
    out[i] = 1.0f / (1.0f + expf(-s));
}

// ---------------------------------------------------------------------------
// Launch: detect -> init -> scatter -> mid -> scatter -> final.
// ---------------------------------------------------------------------------
extern "C" void kernel_launch(void* const* d_in, const int* in_sizes, int n_in,
                              void* d_out, int out_size) {
    const float* x  = (const float*)d_in[0];
    const void*  ei = (const void*)d_in[1];
    const float* W  = (const float*)d_in[2];
    const float* fw = (const float*)d_in[3];
    float* out = (float*)d_out;

    int N = in_sizes[0] / 2;
    long long E = (long long)in_sizes[1] / 2;

    const int TB = 256;
    int nb = (N + TB - 1) / TB;
    const int SCATTER_BLOCKS = 8192;   // R3-proven: ~2M threads over 8M quads

    k_detect<<<1, 256>>>((const long long*)ei, E, N);
    k_init<<<nb, TB>>>((const float2*)x, N);
    k_scatter<<<SCATTER_BLOCKS, TB>>>(ei, E);
    k_mid<<<nb, TB>>>(W, N);
    k_scatter<<<SCATTER_BLOCKS, TB>>>(ei, E);
    k_final<<<nb, TB>>>(W, fw, out, N);

    (void)n_in; (void)out_size;
}

// round 6
// speedup vs baseline: 1.0296x; 1.0005x over previous
#include <cuda_runtime.h>
#include <math.h>

// ---------------------------------------------------------------------------
// Scratch: node state and aggregation buffer. N = 1,000,000 fits in 1<<20.
// ---------------------------------------------------------------------------
#define MAXN (1 << 20)
__device__ float2 g_xn[MAXN];
__device__ float2 g_agg[MAXN];
__device__ int    g_idx64;   // 1 if edge_index is int64, 0 if int32

#define EPSF 1e-15f

__device__ __forceinline__ void red_add_f32x2(float2* p, float vx, float vy) {
    asm volatile("red.global.add.v2.f32 [%0], {%1, %2};"
                 :: "l"(p), "f"(vx), "f"(vy)
                 : "memory");
}

// L2-only 8-byte gather (random access; skip the L1 stage).
__device__ __forceinline__ float2 ldcg_f2(const float2* p) {
    float2 r;
    asm volatile("ld.global.cg.v2.f32 {%0, %1}, [%2];"
                 : "=f"(r.x), "=f"(r.y) : "l"(p));
    return r;
}

// ---------------------------------------------------------------------------
// Kernel 1: normalize x into g_xn (2 nodes/thread, float4), zero g_agg.
// Block 0 additionally performs the index-dtype detection (int32 vs int64):
// read first 2048 8-byte words as int64; any value outside [0,N) => int32.
// ---------------------------------------------------------------------------
__global__ void k_init(const float4* __restrict__ x, int Npairs, int N,
                       const long long* __restrict__ ei, long long n_words) {
    int i = blockIdx.x * blockDim.x + threadIdx.x;
    if (i < Npairs) {
        float4 v = x[i];   // two nodes: (v.x,v.y) and (v.z,v.w)
        float inv0 = 1.0f / (sqrtf(v.x * v.x + v.y * v.y) + EPSF);
        float inv1 = 1.0f / (sqrtf(v.z * v.z + v.w * v.w) + EPSF);
        ((float4*)g_xn)[i] = make_float4(v.x * inv0, v.y * inv0,
                                         v.z * inv1, v.w * inv1);
        ((float4*)g_agg)[i] = make_float4(0.f, 0.f, 0.f, 0.f);
    }
    if (blockIdx.x == 0) {
        __shared__ int bad;
        if (threadIdx.x == 0) bad = 0;
        __syncthreads();
        long long lim = n_words < 2048 ? n_words : 2048;
        int local_bad = 0;
        for (long long w = threadIdx.x; w < lim; w += blockDim.x) {
            long long v = ei[w];
            if (v < 0 || v >= (long long)N) local_bad = 1;
        }
        if (local_bad) bad = 1;
        __syncthreads();
        if (threadIdx.x == 0) g_idx64 = bad ? 0 : 1;
    }
}

// ---------------------------------------------------------------------------
// Kernel 2: edge scatter: g_agg[dst[e]] += g_xn[src[e]].
// One quad (4 edges) per thread, no grid-stride loop. Index loads streamed
// (__ldcs); gathers L2-only (__ldcg); 4 independent gathers batched before
// the 4 reds. Runs at the LTS sector wall (~32B per random access).
// ---------------------------------------------------------------------------
__global__ void __launch_bounds__(256) k_scatter(const void* __restrict__ eiv, long long E) {
    long long q = (long long)blockIdx.x * blockDim.x + threadIdx.x;

    if (g_idx64 == 0) {
        const int* src = (const int*)eiv;
        const int* dst = src + E;
        long long quads = E >> 2;
        if (q < quads) {
            int4 s = __ldcs((const int4*)(src + 4 * q));
            int4 d = __ldcs((const int4*)(dst + 4 * q));
            float2 v0 = ldcg_f2(&g_xn[s.x]);
            float2 v1 = ldcg_f2(&g_xn[s.y]);
            float2 v2 = ldcg_f2(&g_xn[s.z]);
            float2 v3 = ldcg_f2(&g_xn[s.w]);
            red_add_f32x2(&g_agg[d.x], v0.x, v0.y);
            red_add_f32x2(&g_agg[d.y], v1.x, v1.y);
            red_add_f32x2(&g_agg[d.z], v2.x, v2.y);
            red_add_f32x2(&g_agg[d.w], v3.x, v3.y);
        }
        if (q == 0) {
            for (long long e = quads * 4; e < E; e++) {
                float2 v = ldcg_f2(&g_xn[src[e]]);
                red_add_f32x2(&g_agg[dst[e]], v.x, v.y);
            }
        }
    } else {
        const long long* src = (const long long*)eiv;
        const long long* dst = src + E;
        long long quads = (E + 3) >> 2;  // same grid covers int64 path
        if (q < (E >> 2)) {
            longlong2 s0 = __ldcs((const longlong2*)(src + 4 * q));
            longlong2 s1 = __ldcs((const longlong2*)(src + 4 * q) + 1);
            longlong2 d0 = __ldcs((const longlong2*)(dst + 4 * q));
            longlong2 d1 = __ldcs((const longlong2*)(dst + 4 * q) + 1);
            float2 v0 = ldcg_f2(&g_xn[(int)s0.x]);
            float2 v1 = ldcg_f2(&g_xn[(int)s0.y]);
            float2 v2 = ldcg_f2(&g_xn[(int)s1.x]);
            float2 v3 = ldcg_f2(&g_xn[(int)s1.y]);
            red_add_f32x2(&g_agg[(int)d0.x], v0.x, v0.y);
            red_add_f32x2(&g_agg[(int)d0.y], v1.x, v1.y);
            red_add_f32x2(&g_agg[(int)d1.x], v2.x, v2.y);
            red_add_f32x2(&g_agg[(int)d1.y], v3.x, v3.y);
        }
        if (q == 0) {
            for (long long e = (E >> 2) * 4; e < E; e++) {
                float2 v = ldcg_f2(&g_xn[(int)src[e]]);
                red_add_f32x2(&g_agg[(int)dst[e]], v.x, v.y);
            }
        }
        (void)quads;
    }
}

// ---------------------------------------------------------------------------
// Kernel 3: mid-iteration: y = relu(agg @ W); renormalize; zero g_agg.
// 2 nodes per thread via float4.
// ---------------------------------------------------------------------------
__global__ void k_mid(const float* __restrict__ W, int Npairs) {
    int i = blockIdx.x * blockDim.x + threadIdx.x;
    if (i >= Npairs) return;
    float w00 = W[0], w01 = W[1], w10 = W[2], w11 = W[3];
    float4 a = ((const float4*)g_agg)[i];
    float y0 = fmaxf(fmaf(a.y, w10, a.x * w00), 0.0f);
    float y1 = fmaxf(fmaf(a.y, w11, a.x * w01), 0.0f);
    float y2 = fmaxf(fmaf(a.w, w10, a.z * w00), 0.0f);
    float y3 = fmaxf(fmaf(a.w, w11, a.z * w01), 0.0f);
    float inv0 = 1.0f / (sqrtf(y0 * y0 + y1 * y1) + EPSF);
    float inv1 = 1.0f / (sqrtf(y2 * y2 + y3 * y3) + EPSF);
    ((float4*)g_xn)[i] = make_float4(y0 * inv0, y1 * inv0, y2 * inv1, y3 * inv1);
    ((float4*)g_agg)[i] = make_float4(0.f, 0.f, 0.f, 0.f);
}

// ---------------------------------------------------------------------------
// Kernel 4: final: y = relu(agg @ W); out = sigmoid(y . final_weight).
// 2 nodes per thread.
// ---------------------------------------------------------------------------
__global__ void k_final(const float* __restrict__ W,
                        const float* __restrict__ fw,
                        float2* __restrict__ out, int Npairs) {
    int i = blockIdx.x * blockDim.x + threadIdx.x;
    if (i >= Npairs) return;
    float w00 = W[0], w01 = W[1], w10 = W[2], w11 = W[3];
    float f0 = fw[0], f1 = fw[1];
    float4 a = ((const float4*)g_agg)[i];
    float y0 = fmaxf(fmaf(a.y, w10, a.x * w00), 0.0f);
    float y1 = fmaxf(fmaf(a.y, w11, a.x * w01), 0.0f);
    float y2 = fmaxf(fmaf(a.w, w10, a.z * w00), 0.0f);
    float y3 = fmaxf(fmaf(a.w, w11, a.z * w01), 0.0f);
    float s0 = fmaf(y1, f1, y0 * f0);
    float s1 = fmaf(y3, f1, y2 * f0);
    out[i] = make_float2(1.0f / (1.0f + expf(-s0)),
                         1.0f / (1.0f + expf(-s1)));
}

// ---------------------------------------------------------------------------
// Launch: init(+detect) -> scatter -> mid -> scatter -> final.
// Graph-capturable, allocation-free, no syncs.
// ---------------------------------------------------------------------------
extern "C" void kernel_launch(void* const* d_in, const int* in_sizes, int n_in,
                              void* d_out, int out_size) {
    const float* x  = (const float*)d_in[0];
    const void*  ei = (const void*)d_in[1];
    const float* W  = (const float*)d_in[2];
    const float* fw = (const float*)d_in[3];
    float2* out = (float2*)d_out;

    int N = in_sizes[0] / 2;          // N is even (1,000,000)
    int Npairs = N / 2;
    long long E = (long long)in_sizes[1] / 2;
    long long quads = E >> 2;

    const int TB = 256;
    int nb_pairs = (Npairs + TB - 1) / TB;
    int nb_scatter = (int)((quads + TB - 1) / TB);   // one quad per thread

    k_init<<<nb_pairs, TB>>>((const float4*)x, Npairs, N,
                             (const long long*)ei, E);
    k_scatter<<<nb_scatter, TB>>>(ei, E);
    k_mid<<<nb_pairs, TB>>>(W, Npairs);
    k_scatter<<<nb_scatter, TB>>>(ei, E);
    k_final<<<nb_pairs, TB>>>(W, fw, out, Npairs);

    (void)n_in; (void)out_size;
}